// round 5
// baseline (speedup 1.0000x reference)
#include <cuda_runtime.h>

// Closed form of the whole circuit:
//   e_w = cos(theta_w) * prod_{k<=w} cos(x_k)  -  sin(theta_w) * sin(x_w) * sin(x_{w+1})
// with sin(x_4) := 1.
//
// Memory-latency bound kernel: loads are issued via asm volatile so ptxas
// cannot sink them (round 4 showed regs=32 => loads were serialized and
// MLP collapsed to ~1). 8 elements/thread, loads first, weight trig
// overlapped under the load latency.

#define ELTS 8
#define BLOCK 128

__global__ void __launch_bounds__(BLOCK)
qlayer_kernel(const float* __restrict__ x, const float* __restrict__ w,
              float* __restrict__ out, int n) {
    int t = blockIdx.x * blockDim.x + threadIdx.x;
    long b0 = (long)t * ELTS;

    if (b0 + ELTS <= (long)n) {
        const float4* xp = reinterpret_cast<const float4*>(x) + b0 * 2;

        // 8 independent 16B loads, pinned in issue order (MLP_p1 = 8).
        float4 xv[ELTS];
#pragma unroll
        for (int e = 0; e < ELTS; e++) {
            asm volatile("ld.global.nc.v4.f32 {%0,%1,%2,%3}, [%4];"
                         : "=f"(xv[e].x), "=f"(xv[e].y),
                           "=f"(xv[e].z), "=f"(xv[e].w)
                         : "l"(xp + e * 2));
        }

        // Weight trig (uniform, L2 broadcast) — overlaps the load latency.
        float4 wv = *reinterpret_cast<const float4*>(w);
        float sw0, cw0, sw1, cw1, sw2, cw2, sw3, cw3;
        __sincosf(wv.x, &sw0, &cw0);
        __sincosf(wv.y, &sw1, &cw1);
        __sincosf(wv.z, &sw2, &cw2);
        __sincosf(wv.w, &sw3, &cw3);

        float4* op = reinterpret_cast<float4*>(out) + b0;
#pragma unroll
        for (int e = 0; e < ELTS; e++) {
            float s0, c0, s1, c1, s2, c2, s3, c3;
            __sincosf(xv[e].x, &s0, &c0);
            __sincosf(xv[e].y, &s1, &c1);
            __sincosf(xv[e].z, &s2, &c2);
            __sincosf(xv[e].w, &s3, &c3);

            float d0 = c0;
            float d1 = d0 * c1;
            float d2 = d1 * c2;
            float d3 = d2 * c3;

            float4 o;
            o.x = fmaf(cw0, d0, -sw0 * (s0 * s1));
            o.y = fmaf(cw1, d1, -sw1 * (s1 * s2));
            o.z = fmaf(cw2, d2, -sw2 * (s2 * s3));
            o.w = fmaf(cw3, d3, -sw3 * s3);
            op[e] = o;
        }
    } else {
        // Tail (empty when n % (BLOCK*ELTS) == 0; B = 1M is).
        float4 wv = *reinterpret_cast<const float4*>(w);
        float sw0, cw0, sw1, cw1, sw2, cw2, sw3, cw3;
        __sincosf(wv.x, &sw0, &cw0);
        __sincosf(wv.y, &sw1, &cw1);
        __sincosf(wv.z, &sw2, &cw2);
        __sincosf(wv.w, &sw3, &cw3);

        for (long b = b0; b < (long)n; b++) {
            float4 xv = reinterpret_cast<const float4*>(x)[b * 2];
            float s0, c0, s1, c1, s2, c2, s3, c3;
            __sincosf(xv.x, &s0, &c0);
            __sincosf(xv.y, &s1, &c1);
            __sincosf(xv.z, &s2, &c2);
            __sincosf(xv.w, &s3, &c3);

            float d0 = c0;
            float d1 = d0 * c1;
            float d2 = d1 * c2;
            float d3 = d2 * c3;

            float4 o;
            o.x = fmaf(cw0, d0, -sw0 * (s0 * s1));
            o.y = fmaf(cw1, d1, -sw1 * (s1 * s2));
            o.z = fmaf(cw2, d2, -sw2 * (s2 * s3));
            o.w = fmaf(cw3, d3, -sw3 * s3);
            reinterpret_cast<float4*>(out)[b] = o;
        }
    }
}

extern "C" void kernel_launch(void* const* d_in, const int* in_sizes, int n_in,
                              void* d_out, int out_size) {
    const float* x = (const float*)d_in[0];        // [B, 8]
    const float* weights = (const float*)d_in[1];  // [4]
    float* out = (float*)d_out;                    // [B, 4]
    int n = in_sizes[0] / 8;

    int elts_per_block = BLOCK * ELTS;
    int blocks = (n + elts_per_block - 1) / elts_per_block;
    qlayer_kernel<<<blocks, BLOCK>>>(x, weights, out, n);
}

// round 6
// speedup vs baseline: 1.3500x; 1.3500x over previous
#include <cuda_runtime.h>

// Closed form of the whole circuit:
//   e_w = cos(theta_w) * prod_{k<=w} cos(x_k)  -  sin(theta_w) * sin(x_w) * sin(x_{w+1})
// with sin(x_4) := 1.
//
// Loads go through cp.async (LDGSTS) so memory-level parallelism is
// structural, not at ptxas's discretion: rounds 3-5 proved ptxas always
// interleaves consumers between register loads, collapsing MLP to ~1.
// cp.async has no destination register -> all ELTS transfers are in flight
// before the single wait.

#define ELTS 4
#define BLOCK 256
#define TILE (BLOCK * ELTS)

__global__ void __launch_bounds__(BLOCK)
qlayer_kernel(const float* __restrict__ x, const float* __restrict__ w,
              float* __restrict__ out, int n) {
    __shared__ float4 sx[TILE];

    int tid = threadIdx.x;
    int base = blockIdx.x * TILE;

    unsigned smem_base;
    asm("{ .reg .u64 t; cvta.to.shared.u64 t, %1; cvt.u32.u64 %0, t; }"
        : "=r"(smem_base) : "l"(sx));

    if (base + TILE <= n) {
        // Issue ELTS independent 16B global->shared copies (no scoreboard
        // coupling to compute), coalesced: within a warp-op lanes are 32B apart.
#pragma unroll
        for (int e = 0; e < ELTS; e++) {
            int b = base + e * BLOCK + tid;
            const float* gp = x + (long)b * 8;          // first 16B of the row
            unsigned sp = smem_base + (e * BLOCK + tid) * 16;
            asm volatile("cp.async.cg.shared.global [%0], [%1], 16;"
                         :: "r"(sp), "l"(gp));
        }
        asm volatile("cp.async.commit_group;");

        // Weight trig (uniform) overlaps the async copies.
        float4 wv = *reinterpret_cast<const float4*>(w);
        float sw0, cw0, sw1, cw1, sw2, cw2, sw3, cw3;
        __sincosf(wv.x, &sw0, &cw0);
        __sincosf(wv.y, &sw1, &cw1);
        __sincosf(wv.z, &sw2, &cw2);
        __sincosf(wv.w, &sw3, &cw3);

        asm volatile("cp.async.wait_group 0;" ::: "memory");
        // Each thread reads only slots it wrote itself -> no __syncthreads.

#pragma unroll
        for (int e = 0; e < ELTS; e++) {
            int b = base + e * BLOCK + tid;
            float4 xv = sx[e * BLOCK + tid];

            float s0, c0, s1, c1, s2, c2, s3, c3;
            __sincosf(xv.x, &s0, &c0);
            __sincosf(xv.y, &s1, &c1);
            __sincosf(xv.z, &s2, &c2);
            __sincosf(xv.w, &s3, &c3);

            float d0 = c0;
            float d1 = d0 * c1;
            float d2 = d1 * c2;
            float d3 = d2 * c3;

            float4 o;
            o.x = fmaf(cw0, d0, -sw0 * (s0 * s1));
            o.y = fmaf(cw1, d1, -sw1 * (s1 * s2));
            o.z = fmaf(cw2, d2, -sw2 * (s2 * s3));
            o.w = fmaf(cw3, d3, -sw3 * s3);
            reinterpret_cast<float4*>(out)[b] = o;
        }
    } else {
        // Tail (empty for B = 1M; kept for generality).
        float4 wv = *reinterpret_cast<const float4*>(w);
        float sw0, cw0, sw1, cw1, sw2, cw2, sw3, cw3;
        __sincosf(wv.x, &sw0, &cw0);
        __sincosf(wv.y, &sw1, &cw1);
        __sincosf(wv.z, &sw2, &cw2);
        __sincosf(wv.w, &sw3, &cw3);

        for (int b = base + tid; b < n; b += BLOCK) {
            float4 xv = reinterpret_cast<const float4*>(x)[(long)b * 2];
            float s0, c0, s1, c1, s2, c2, s3, c3;
            __sincosf(xv.x, &s0, &c0);
            __sincosf(xv.y, &s1, &c1);
            __sincosf(xv.z, &s2, &c2);
            __sincosf(xv.w, &s3, &c3);

            float d0 = c0;
            float d1 = d0 * c1;
            float d2 = d1 * c2;
            float d3 = d2 * c3;

            float4 o;
            o.x = fmaf(cw0, d0, -sw0 * (s0 * s1));
            o.y = fmaf(cw1, d1, -sw1 * (s1 * s2));
            o.z = fmaf(cw2, d2, -sw2 * (s2 * s3));
            o.w = fmaf(cw3, d3, -sw3 * s3);
            reinterpret_cast<float4*>(out)[b] = o;
        }
    }
}

extern "C" void kernel_launch(void* const* d_in, const int* in_sizes, int n_in,
                              void* d_out, int out_size) {
    const float* x = (const float*)d_in[0];        // [B, 8]
    const float* weights = (const float*)d_in[1];  // [4]
    float* out = (float*)d_out;                    // [B, 4]
    int n = in_sizes[0] / 8;

    int blocks = (n + TILE - 1) / TILE;
    qlayer_kernel<<<blocks, BLOCK>>>(x, weights, out, n);
}